// round 2
// baseline (speedup 1.0000x reference)
#include <cuda_runtime.h>

#define NN 50000
#define NE 600000
#define DD 128
#define NL 4
#define NG 512
#define NC 10

// ---- scratch (device globals: allocation-free) ----
__device__ float g_H[NN * DD];   // layer input h
__device__ float g_Z[NN * DD];   // z buffer ((1+eps)h + agg, later z2)
__device__ float g_T[NN * DD];   // MLP hidden
__device__ float g_sum[DD];
__device__ float g_sqs[DD];
__device__ float g_scale[DD];
__device__ float g_shift[DD];
__device__ float g_pool[NG * NL * DD];

// index scratch (dtype-normalized to int32)
__device__ int g_src[NE];
__device__ int g_dst[NE];
__device__ int g_batch[NN];
__device__ int g_mode_ei;   // 1 = source buffer is int64
__device__ int g_mode_b;

__device__ __forceinline__ void red_add_v4(float* p, float4 v) {
    asm volatile("red.global.add.v4.f32 [%0], {%1, %2, %3, %4};"
                 :: "l"(p), "f"(v.x), "f"(v.y), "f"(v.z), "f"(v.w)
                 : "memory");
}

// ---------------- index dtype detection + conversion ----------------
__global__ void flags_init_kernel() {
    g_mode_ei = 1;
    g_mode_b = 1;
}

// Scan odd 32-bit words within the int32-sized footprint of each buffer.
// If any is nonzero, buffer cannot be int64 (values < 2^31 -> hi word == 0).
__global__ void detect_kernel(const int* __restrict__ ei32,
                              const int* __restrict__ b32) {
    int i = blockIdx.x * blockDim.x + threadIdx.x;
    int idx = 2 * i + 1;
    if (idx < 2 * NE) {                 // within 1.2M-word (int32) footprint
        if (ei32[idx] != 0) atomicExch(&g_mode_ei, 0);
    }
    if (idx < NN) {                     // within 50000-word footprint
        if (b32[idx] != 0) atomicExch(&g_mode_b, 0);
    }
}

__global__ void convert_kernel(const int* __restrict__ ei32,
                               const int* __restrict__ b32) {
    int i = blockIdx.x * blockDim.x + threadIdx.x;
    int m_ei = g_mode_ei, m_b = g_mode_b;
    if (i < NE) {
        g_src[i] = m_ei ? ei32[2 * i]            : ei32[i];
        g_dst[i] = m_ei ? ei32[2 * (NE + i)]     : ei32[NE + i];
    }
    if (i < NN) {
        g_batch[i] = m_b ? b32[2 * i] : b32[i];
    }
}

// ---------------- layer kernels ----------------

// Z = (1+eps[l]) * h ; block 0 additionally zeroes BN stats and this layer's pool slice
__global__ void zinit_kernel(const float* __restrict__ x,
                             const float* __restrict__ eps, int l) {
    int i = blockIdx.x * blockDim.x + threadIdx.x;
    const float* h = l ? g_H : x;
    if (i < NN * DD / 4) {
        float e = 1.0f + __ldg(&eps[l]);
        float4 v = ((const float4*)h)[i];
        v.x *= e; v.y *= e; v.z *= e; v.w *= e;
        ((float4*)g_Z)[i] = v;
    }
    if (blockIdx.x == 0) {
        for (int j = threadIdx.x; j < DD; j += blockDim.x) {
            g_sum[j] = 0.f; g_sqs[j] = 0.f;
        }
        for (int j = threadIdx.x; j < NG * DD; j += blockDim.x)
            g_pool[(j >> 7) * (NL * DD) + l * DD + (j & 127)] = 0.f;
    }
}

// one warp per edge: gather h[src] row (512B, coalesced), red.add into Z[dst]
__global__ void edge_kernel(const float* __restrict__ x, int l) {
    long long t = (long long)blockIdx.x * blockDim.x + threadIdx.x;
    if (t >= (long long)NE * 32) return;
    int e = (int)(t >> 5);
    int c = ((int)t & 31) << 2;
    const float* h = l ? g_H : x;
    int s = __ldg(&g_src[e]);
    int d = __ldg(&g_dst[e]);
    float4 v = *(const float4*)(h + (size_t)s * DD + c);
    red_add_v4(g_Z + (size_t)d * DD + c, v);
}

// C = [relu](A @ W + bias); A,C selected from scratch buffers by 'ab'
// BM=128, BN=128(=D), full-K weight tile in smem, 8x8 micro-tile, 256 threads
__global__ __launch_bounds__(256) void gemm_kernel(
    const float* __restrict__ Wt, const float* __restrict__ bias,
    int M, int relu, int ab) {
    extern __shared__ float smem[];
    float* Bs = smem;            // [128][128] = W (k-major rows)
    float* As = smem + DD * DD;  // [128][128] = A tile (m-major rows)
    const float* A = ab ? g_T : g_Z;
    float* Cout    = ab ? g_Z : g_T;

    int tid = threadIdx.x;
    int row0 = blockIdx.x * 128;

    #pragma unroll 4
    for (int i = tid; i < DD * DD / 4; i += 256)
        ((float4*)Bs)[i] = ((const float4*)Wt)[i];
    #pragma unroll 4
    for (int i = tid; i < 128 * DD / 4; i += 256) {
        int m = i >> 5;
        int k4 = i & 31;
        int gm = row0 + m;
        float4 v = make_float4(0.f, 0.f, 0.f, 0.f);
        if (gm < M) v = ((const float4*)(A + (size_t)gm * DD))[k4];
        ((float4*)As)[i] = v;
    }
    __syncthreads();

    int txn = (tid & 15) * 8;
    int tym = (tid >> 4) * 8;
    float acc[8][8];
    #pragma unroll
    for (int i = 0; i < 8; i++)
        #pragma unroll
        for (int j = 0; j < 8; j++) acc[i][j] = 0.f;

    #pragma unroll 8
    for (int k = 0; k < DD; k++) {
        float4 b0 = *(const float4*)&Bs[k * DD + txn];
        float4 b1 = *(const float4*)&Bs[k * DD + txn + 4];
        #pragma unroll
        for (int i = 0; i < 8; i++) {
            float a = As[(tym + i) * DD + k];
            acc[i][0] += a * b0.x; acc[i][1] += a * b0.y;
            acc[i][2] += a * b0.z; acc[i][3] += a * b0.w;
            acc[i][4] += a * b1.x; acc[i][5] += a * b1.y;
            acc[i][6] += a * b1.z; acc[i][7] += a * b1.w;
        }
    }

    float4 bb0 = *(const float4*)&bias[txn];
    float4 bb1 = *(const float4*)&bias[txn + 4];
    #pragma unroll
    for (int i = 0; i < 8; i++) {
        int gm = row0 + tym + i;
        if (gm >= M) continue;
        float4 o0, o1;
        o0.x = acc[i][0] + bb0.x; o0.y = acc[i][1] + bb0.y;
        o0.z = acc[i][2] + bb0.z; o0.w = acc[i][3] + bb0.w;
        o1.x = acc[i][4] + bb1.x; o1.y = acc[i][5] + bb1.y;
        o1.z = acc[i][6] + bb1.z; o1.w = acc[i][7] + bb1.w;
        if (relu) {
            o0.x = fmaxf(o0.x, 0.f); o0.y = fmaxf(o0.y, 0.f);
            o0.z = fmaxf(o0.z, 0.f); o0.w = fmaxf(o0.w, 0.f);
            o1.x = fmaxf(o1.x, 0.f); o1.y = fmaxf(o1.y, 0.f);
            o1.z = fmaxf(o1.z, 0.f); o1.w = fmaxf(o1.w, 0.f);
        }
        float4* dst = (float4*)(Cout + (size_t)gm * DD + txn);
        dst[0] = o0; dst[1] = o1;
    }
}

// per-channel sum / sumsq over g_Z
__global__ void bn_stats_kernel() {
    int tid = threadIdx.x;
    int c = tid & 127;
    int g = tid >> 7;  // 0 or 1
    float s = 0.f, q = 0.f;
    for (int r = blockIdx.x * 2 + g; r < NN; r += gridDim.x * 2) {
        float z = g_Z[(size_t)r * DD + c];
        s += z; q += z * z;
    }
    __shared__ float sh[512];
    sh[tid] = s; sh[256 + tid] = q;
    __syncthreads();
    if (tid < 128) {
        atomicAdd(&g_sum[c], sh[tid] + sh[tid + 128]);
        atomicAdd(&g_sqs[c], sh[256 + tid] + sh[256 + tid + 128]);
    }
}

__global__ void bn_finalize_kernel(const float* __restrict__ gamma,
                                   const float* __restrict__ beta, int l) {
    int c = threadIdx.x;
    float mean = g_sum[c] * (1.0f / NN);
    float var = g_sqs[c] * (1.0f / NN) - mean * mean;
    float sc = gamma[l * DD + c] * rsqrtf(var + 1e-5f);
    g_scale[c] = sc;
    g_shift[c] = beta[l * DD + c] - mean * sc;
}

// h = relu(z*scale + shift); pool[batch[r]] += h (per-layer column slice)
__global__ void bn_relu_pool_kernel(int l) {
    int i = blockIdx.x * blockDim.x + threadIdx.x;
    if (i >= NN * DD / 4) return;
    int r = i >> 5;
    int c4 = (i & 31) << 2;
    float4 z = ((const float4*)g_Z)[i];
    float4 sc = *(const float4*)&g_scale[c4];
    float4 sf = *(const float4*)&g_shift[c4];
    float4 hv;
    hv.x = fmaxf(z.x * sc.x + sf.x, 0.f);
    hv.y = fmaxf(z.y * sc.y + sf.y, 0.f);
    hv.z = fmaxf(z.z * sc.z + sf.z, 0.f);
    hv.w = fmaxf(z.w * sc.w + sf.w, 0.f);
    ((float4*)g_H)[i] = hv;
    int b = __ldg(&g_batch[r]);
    red_add_v4(&g_pool[(size_t)b * (NL * DD) + l * DD + c4], hv);
}

// out[g][cls] = blin[cls] + pool[g] . Wlin[:,cls]
__global__ void final_kernel(const float* __restrict__ Wlin,
                             const float* __restrict__ blin,
                             float* __restrict__ out) {
    int gph = blockIdx.x;
    int lane = threadIdx.x;
    if (lane < NC) {
        float acc = blin[lane];
        const float* prow = &g_pool[(size_t)gph * (NL * DD)];
        for (int k = 0; k < NL * DD; k++)
            acc += prow[k] * Wlin[k * NC + lane];
        out[gph * NC + lane] = acc;
    }
}

extern "C" void kernel_launch(void* const* d_in, const int* in_sizes, int n_in,
                              void* d_out, int out_size) {
    const float* x     = (const float*)d_in[0];
    const int*   ei32  = (const int*)d_in[1];   // int32 or int64 (auto-detected)
    const int*   b32   = (const int*)d_in[2];
    const float* W1    = (const float*)d_in[3];
    const float* b1    = (const float*)d_in[4];
    const float* W2    = (const float*)d_in[5];
    const float* b2    = (const float*)d_in[6];
    const float* eps   = (const float*)d_in[7];
    const float* gamma = (const float*)d_in[8];
    const float* beta  = (const float*)d_in[9];
    const float* Wlin  = (const float*)d_in[10];
    const float* blin  = (const float*)d_in[11];
    float* out = (float*)d_out;

    const int SMEM = 2 * DD * DD * (int)sizeof(float);  // 128 KB
    cudaFuncSetAttribute(gemm_kernel,
                         cudaFuncAttributeMaxDynamicSharedMemorySize, SMEM);

    // normalize index dtypes
    flags_init_kernel<<<1, 1>>>();
    detect_kernel<<<(NE + 255) / 256, 256>>>(ei32, b32);
    convert_kernel<<<(NE + 255) / 256, 256>>>(ei32, b32);

    int zgrid = (NN * DD / 4 + 255) / 256;
    long long etot = (long long)NE * 32;
    int egrid = (int)((etot + 255) / 256);
    int ggrid = (NN + 127) / 128;

    for (int l = 0; l < NL; l++) {
        zinit_kernel<<<zgrid, 256>>>(x, eps, l);
        edge_kernel<<<egrid, 256>>>(x, l);
        gemm_kernel<<<ggrid, 256, SMEM>>>(W1 + (size_t)l * DD * DD, b1 + l * DD,
                                          NN, 1, 0);  // T = relu(Z@W1+b1)
        gemm_kernel<<<ggrid, 256, SMEM>>>(W2 + (size_t)l * DD * DD, b2 + l * DD,
                                          NN, 0, 1);  // Z = T@W2+b2
        bn_stats_kernel<<<250, 256>>>();
        bn_finalize_kernel<<<1, DD>>>(gamma, beta, l);
        bn_relu_pool_kernel<<<zgrid, 256>>>(l);
    }
    final_kernel<<<NG, 32>>>(Wlin, blin, out);
}

// round 6
// speedup vs baseline: 1.3081x; 1.3081x over previous
#include <cuda_runtime.h>
#include <cstdint>

#define NN 50000
#define NE 600000
#define DD 128
#define NL 4
#define NG 512
#define NC 10
#define AST 132   // padded smem stride (floats)

// ---- scratch (device globals: allocation-free) ----
__device__ float g_H[NN * DD];
__device__ float g_Z[NN * DD];
__device__ float g_T[NN * DD];
__device__ float g_sum[DD];
__device__ float g_sqs[DD];
__device__ float g_scale[DD];
__device__ float g_shift[DD];
__device__ float g_pool[NG * NL * DD];
__device__ uint32_t g_Wt[2][NL][DD * AST];   // transposed, padded, tf32-converted

__device__ int g_src[NE];
__device__ int g_dst[NE];
__device__ int g_batch[NN];
__device__ int g_deg[NN];
__device__ int g_ptr[NN + 1];
__device__ int g_off[NN];
__device__ int g_csr_src[NE];
__device__ int g_mode_ei;
__device__ int g_mode_b;

__device__ __forceinline__ void red_add_v4(float* p, float4 v) {
    asm volatile("red.global.add.v4.f32 [%0], {%1, %2, %3, %4};"
                 :: "l"(p), "f"(v.x), "f"(v.y), "f"(v.z), "f"(v.w)
                 : "memory");
}
__device__ __forceinline__ uint32_t f2tf32(float f) {
    uint32_t u;
    asm("cvt.rna.tf32.f32 %0, %1;" : "=r"(u) : "f"(f));
    return u;
}
__device__ __forceinline__ void mma_tf32(float& c0, float& c1, float& c2, float& c3,
                                         uint32_t a0, uint32_t a1, uint32_t a2, uint32_t a3,
                                         uint32_t b0, uint32_t b1) {
    asm volatile(
        "mma.sync.aligned.m16n8k8.row.col.f32.tf32.tf32.f32 "
        "{%0,%1,%2,%3}, {%4,%5,%6,%7}, {%8,%9}, {%0,%1,%2,%3};"
        : "+f"(c0), "+f"(c1), "+f"(c2), "+f"(c3)
        : "r"(a0), "r"(a1), "r"(a2), "r"(a3), "r"(b0), "r"(b1));
}

// ---------------- preamble: dtype detect, CSR build, weight prep ----------------
__global__ void flags_init_kernel() { g_mode_ei = 1; g_mode_b = 1; }

__global__ void detect_kernel(const int* __restrict__ ei32,
                              const int* __restrict__ b32) {
    int i = blockIdx.x * blockDim.x + threadIdx.x;
    int idx = 2 * i + 1;
    if (idx < 2 * NE) { if (ei32[idx] != 0) atomicExch(&g_mode_ei, 0); }
    if (idx < NN)     { if (b32[idx]  != 0) atomicExch(&g_mode_b, 0); }
}

__global__ void convert_kernel(const int* __restrict__ ei32,
                               const int* __restrict__ b32) {
    int i = blockIdx.x * blockDim.x + threadIdx.x;
    int m_ei = g_mode_ei, m_b = g_mode_b;
    if (i < NE) {
        g_src[i] = m_ei ? ei32[2 * i]        : ei32[i];
        g_dst[i] = m_ei ? ei32[2 * (NE + i)] : ei32[NE + i];
    }
    if (i < NN) g_batch[i] = m_b ? b32[2 * i] : b32[i];
}

// zero pool + BN accumulators + degree counters (every launch)
__global__ void zero_kernel() {
    int i = blockIdx.x * blockDim.x + threadIdx.x;
    if (i < NG * NL * DD) g_pool[i] = 0.f;
    if (i < NN) g_deg[i] = 0;
    if (i < DD) { g_sum[i] = 0.f; g_sqs[i] = 0.f; }
}

__global__ void hist_kernel() {
    int i = blockIdx.x * blockDim.x + threadIdx.x;
    if (i < NE) atomicAdd(&g_deg[g_dst[i]], 1);
}

// single-block exclusive scan over degrees -> g_ptr, copy to g_off
__global__ void scan_kernel() {
    __shared__ int sh[1024];
    int t = threadIdx.x;
    const int CH = (NN + 1023) / 1024;   // 49
    int b0 = t * CH, b1 = min(b0 + CH, NN);
    int s = 0;
    for (int i = b0; i < b1; i++) s += g_deg[i];
    sh[t] = s;
    __syncthreads();
    for (int off = 1; off < 1024; off <<= 1) {
        int v = (t >= off) ? sh[t - off] : 0;
        __syncthreads();
        sh[t] += v;
        __syncthreads();
    }
    int run = (t > 0) ? sh[t - 1] : 0;
    for (int i = b0; i < b1; i++) {
        g_ptr[i] = run; g_off[i] = run;
        run += g_deg[i];
    }
    if (t == 0) g_ptr[NN] = NE;
}

__global__ void scatter_kernel() {
    int i = blockIdx.x * blockDim.x + threadIdx.x;
    if (i >= NE) return;
    int d = g_dst[i];
    int pos = atomicAdd(&g_off[d], 1);
    g_csr_src[pos] = g_src[i];
}

// transpose + pad + tf32-convert weights: Wt[n*AST + k] = tf32(W[k*DD + n])
__global__ void wprep_kernel(const float* __restrict__ W1,
                             const float* __restrict__ W2) {
    int i = blockIdx.x * blockDim.x + threadIdx.x;   // 2*NL*DD*DD
    if (i >= 2 * NL * DD * DD) return;
    int which = i / (NL * DD * DD);
    int r = i % (NL * DD * DD);
    int l = r / (DD * DD);
    int e = r % (DD * DD);
    int k = e / DD, n = e % DD;
    const float* w = which ? W2 : W1;
    g_Wt[which][l][n * AST + k] = f2tf32(w[l * DD * DD + k * DD + n]);
}

// ---------------- fused (1+eps)*h + CSR neighbor-sum, one warp per node ----------------
__global__ void agg_kernel(const float* __restrict__ x,
                           const float* __restrict__ eps, int l) {
    int warp = (blockIdx.x * blockDim.x + threadIdx.x) >> 5;
    if (warp >= NN) return;
    int lane = threadIdx.x & 31;
    const float* h = l ? g_H : x;
    const float4* hv = (const float4*)h;
    float e = 1.0f + __ldg(&eps[l]);
    float4 a = hv[warp * 32 + lane];
    float4 acc = make_float4(a.x * e, a.y * e, a.z * e, a.w * e);
    int p = __ldg(&g_ptr[warp]);
    int p1 = __ldg(&g_ptr[warp + 1]);
    for (; p + 4 <= p1; p += 4) {
        int s0 = __ldg(&g_csr_src[p]);
        int s1 = __ldg(&g_csr_src[p + 1]);
        int s2 = __ldg(&g_csr_src[p + 2]);
        int s3 = __ldg(&g_csr_src[p + 3]);
        float4 v0 = __ldg(&hv[s0 * 32 + lane]);
        float4 v1 = __ldg(&hv[s1 * 32 + lane]);
        float4 v2 = __ldg(&hv[s2 * 32 + lane]);
        float4 v3 = __ldg(&hv[s3 * 32 + lane]);
        acc.x += v0.x + v1.x + v2.x + v3.x;
        acc.y += v0.y + v1.y + v2.y + v3.y;
        acc.z += v0.z + v1.z + v2.z + v3.z;
        acc.w += v0.w + v1.w + v2.w + v3.w;
    }
    for (; p < p1; p++) {
        int s = __ldg(&g_csr_src[p]);
        float4 v = __ldg(&hv[s * 32 + lane]);
        acc.x += v.x; acc.y += v.y; acc.z += v.z; acc.w += v.w;
    }
    ((float4*)g_Z)[warp * 32 + lane] = acc;
}

// ---------------- mma.sync tf32 GEMM: C = [relu](A @ W + bias) ----------------
// 256 threads, block tile 128x128, full K=128 in smem, warp tile 32x64
#define SMEM_GEMM (2 * DD * AST * 4)

__global__ __launch_bounds__(256, 1)
void gemm_mma_kernel(const uint32_t* __restrict__ Wt,
                     const float* __restrict__ bias,
                     int relu, int ab) {
    extern __shared__ __align__(16) uint32_t smem[];
    uint32_t* As = smem;             // [128][AST]
    uint32_t* Bs = smem + DD * AST;  // [128][AST] (n-major, pre-transposed)
    const float* A = ab ? g_T : g_Z;
    float* Cout    = ab ? g_Z : g_T;

    int tid = threadIdx.x;
    int row0 = blockIdx.x * 128;

    // B: straight padded copy (already tf32 bits)
    #pragma unroll 4
    for (int i = tid; i < DD * AST / 4; i += 256)
        ((uint4*)Bs)[i] = ((const uint4*)Wt)[i];
    // A: row-major load + tf32 convert
    #pragma unroll 4
    for (int i = tid; i < 128 * 32; i += 256) {
        int m = i >> 5;
        int k4 = i & 31;
        int gm = row0 + m;
        float4 v = make_float4(0.f, 0.f, 0.f, 0.f);
        if (gm < NN) v = ((const float4*)(A + (size_t)gm * DD))[k4];
        uint32_t* p = &As[m * AST + k4 * 4];
        p[0] = f2tf32(v.x); p[1] = f2tf32(v.y);
        p[2] = f2tf32(v.z); p[3] = f2tf32(v.w);
    }
    __syncthreads();

    int wid = tid >> 5, lane = tid & 31;
    int wm = (wid & 3) * 32;    // warp M offset
    int wn = (wid >> 2) * 64;   // warp N offset
    int grp = lane >> 2, qid = lane & 3;

    float acc[2][8][4];
    #pragma unroll
    for (int i = 0; i < 2; i++)
        #pragma unroll
        for (int j = 0; j < 8; j++)
            #pragma unroll
            for (int q = 0; q < 4; q++) acc[i][j][q] = 0.f;

    #pragma unroll
    for (int ks = 0; ks < 16; ks++) {
        int k0 = ks * 8;
        uint32_t a[2][4];
        #pragma unroll
        for (int mt = 0; mt < 2; mt++) {
            int r = wm + mt * 16;
            a[mt][0] = As[(r + grp) * AST + k0 + qid];
            a[mt][1] = As[(r + grp + 8) * AST + k0 + qid];
            a[mt][2] = As[(r + grp) * AST + k0 + qid + 4];
            a[mt][3] = As[(r + grp + 8) * AST + k0 + qid + 4];
        }
        #pragma unroll
        for (int nt = 0; nt < 8; nt++) {
            uint32_t b0 = Bs[(wn + nt * 8 + grp) * AST + k0 + qid];
            uint32_t b1 = Bs[(wn + nt * 8 + grp) * AST + k0 + qid + 4];
            #pragma unroll
            for (int mt = 0; mt < 2; mt++)
                mma_tf32(acc[mt][nt][0], acc[mt][nt][1], acc[mt][nt][2], acc[mt][nt][3],
                         a[mt][0], a[mt][1], a[mt][2], a[mt][3], b0, b1);
        }
    }

    // epilogue: c0,c1 -> (r, col..col+1); c2,c3 -> (r+8, ...)
    #pragma unroll
    for (int nt = 0; nt < 8; nt++) {
        int col = wn + nt * 8 + 2 * qid;
        float bv0 = __ldg(&bias[col]);
        float bv1 = __ldg(&bias[col + 1]);
        #pragma unroll
        for (int mt = 0; mt < 2; mt++) {
            int r = row0 + wm + mt * 16 + grp;
            float v0 = acc[mt][nt][0] + bv0;
            float v1 = acc[mt][nt][1] + bv1;
            float v2 = acc[mt][nt][2] + bv0;
            float v3 = acc[mt][nt][3] + bv1;
            if (relu) {
                v0 = fmaxf(v0, 0.f); v1 = fmaxf(v1, 0.f);
                v2 = fmaxf(v2, 0.f); v3 = fmaxf(v3, 0.f);
            }
            if (r < NN)
                *(float2*)(Cout + (size_t)r * DD + col) = make_float2(v0, v1);
            if (r + 8 < NN)
                *(float2*)(Cout + (size_t)(r + 8) * DD + col) = make_float2(v2, v3);
        }
    }
}

// ---------------- BN / pool / final ----------------
__global__ void bn_stats_kernel() {
    int tid = threadIdx.x;
    int c = tid & 127;
    int g = tid >> 7;
    float s = 0.f, q = 0.f;
    for (int r = blockIdx.x * 2 + g; r < NN; r += gridDim.x * 2) {
        float z = g_Z[(size_t)r * DD + c];
        s += z; q += z * z;
    }
    __shared__ float sh[512];
    sh[tid] = s; sh[256 + tid] = q;
    __syncthreads();
    if (tid < 128) {
        atomicAdd(&g_sum[c], sh[tid] + sh[tid + 128]);
        atomicAdd(&g_sqs[c], sh[256 + tid] + sh[256 + tid + 128]);
    }
}

// compute scale/shift, then re-zero accumulators for the next layer
__global__ void bn_finalize_kernel(const float* __restrict__ gamma,
                                   const float* __restrict__ beta, int l) {
    int c = threadIdx.x;
    float mean = g_sum[c] * (1.0f / NN);
    float var = g_sqs[c] * (1.0f / NN) - mean * mean;
    float sc = gamma[l * DD + c] * rsqrtf(var + 1e-5f);
    g_scale[c] = sc;
    g_shift[c] = beta[l * DD + c] - mean * sc;
    g_sum[c] = 0.f;
    g_sqs[c] = 0.f;
}

__global__ void bn_relu_pool_kernel(int l) {
    int i = blockIdx.x * blockDim.x + threadIdx.x;
    if (i >= NN * DD / 4) return;
    int r = i >> 5;
    int c4 = (i & 31) << 2;
    float4 z = ((const float4*)g_Z)[i];
    float4 sc = *(const float4*)&g_scale[c4];
    float4 sf = *(const float4*)&g_shift[c4];
    float4 hv;
    hv.x = fmaxf(z.x * sc.x + sf.x, 0.f);
    hv.y = fmaxf(z.y * sc.y + sf.y, 0.f);
    hv.z = fmaxf(z.z * sc.z + sf.z, 0.f);
    hv.w = fmaxf(z.w * sc.w + sf.w, 0.f);
    ((float4*)g_H)[i] = hv;
    int b = __ldg(&g_batch[r]);
    red_add_v4(&g_pool[(size_t)b * (NL * DD) + l * DD + c4], hv);
}

__global__ void final_kernel(const float* __restrict__ Wlin,
                             const float* __restrict__ blin,
                             float* __restrict__ out) {
    int gph = blockIdx.x;
    int lane = threadIdx.x;
    if (lane < NC) {
        float acc = blin[lane];
        const float* prow = &g_pool[(size_t)gph * (NL * DD)];
        for (int k = 0; k < NL * DD; k++)
            acc += prow[k] * Wlin[k * NC + lane];
        out[gph * NC + lane] = acc;
    }
}

extern "C" void kernel_launch(void* const* d_in, const int* in_sizes, int n_in,
                              void* d_out, int out_size) {
    const float* x     = (const float*)d_in[0];
    const int*   ei32  = (const int*)d_in[1];
    const int*   b32   = (const int*)d_in[2];
    const float* W1    = (const float*)d_in[3];
    const float* b1    = (const float*)d_in[4];
    const float* W2    = (const float*)d_in[5];
    const float* b2    = (const float*)d_in[6];
    const float* eps   = (const float*)d_in[7];
    const float* gamma = (const float*)d_in[8];
    const float* beta  = (const float*)d_in[9];
    const float* Wlin  = (const float*)d_in[10];
    const float* blin  = (const float*)d_in[11];
    float* out = (float*)d_out;

    cudaFuncSetAttribute(gemm_mma_kernel,
                         cudaFuncAttributeMaxDynamicSharedMemorySize, SMEM_GEMM);

    // preamble
    flags_init_kernel<<<1, 1>>>();
    detect_kernel<<<(NE + 255) / 256, 256>>>(ei32, b32);
    convert_kernel<<<(NE + 255) / 256, 256>>>(ei32, b32);
    zero_kernel<<<(NG * NL * DD + 255) / 256, 256>>>();
    hist_kernel<<<(NE + 255) / 256, 256>>>();
    scan_kernel<<<1, 1024>>>();
    scatter_kernel<<<(NE + 255) / 256, 256>>>();
    wprep_kernel<<<(2 * NL * DD * DD + 255) / 256, 256>>>(W1, W2);

    int zgrid = (NN * DD / 4 + 255) / 256;
    int agrid = (NN * 32 + 255) / 256;   // warp per node
    int ggrid = (NN + 127) / 128;        // 391

    uint32_t* wt_base;
    cudaGetSymbolAddress((void**)&wt_base, g_Wt);

    for (int l = 0; l < NL; l++) {
        agg_kernel<<<agrid, 256>>>(x, eps, l);
        gemm_mma_kernel<<<ggrid, 256, SMEM_GEMM>>>(
            wt_base + (size_t)l * DD * AST, b1 + l * DD, 1, 0);            // T = relu(Z@W1+b1)
        gemm_mma_kernel<<<ggrid, 256, SMEM_GEMM>>>(
            wt_base + (size_t)(NL + l) * DD * AST, b2 + l * DD, 0, 1);     // Z = T@W2+b2
        bn_stats_kernel<<<250, 256>>>();
        bn_finalize_kernel<<<1, DD>>>(gamma, beta, l);
        bn_relu_pool_kernel<<<zgrid, 256>>>(l);
    }
    final_kernel<<<NG, 32>>>(Wlin, blin, out);
}

// round 7
// speedup vs baseline: 1.4475x; 1.1065x over previous
#include <cuda_runtime.h>
#include <cstdint>

#define NN 50000
#define NE 600000
#define DD 128
#define NL 4
#define NG 512
#define NC 10
#define AST 132        // padded smem stride (floats)
#define MT 64          // GEMM M tile

// ---- scratch (device globals: allocation-free) ----
__device__ float g_H[NN * DD];
__device__ float g_Z[NN * DD];
__device__ float g_T[NN * DD];
__device__ float g_sum[NL * DD];
__device__ float g_sqs[NL * DD];
__device__ float g_pool[NG * NL * DD];
__device__ uint32_t g_Wt[2][NL][DD * AST];   // transposed, padded, tf32-converted

__device__ int g_src[NE];
__device__ int g_dst[NE];
__device__ int g_batch[NN];
__device__ int g_deg[NN];
__device__ int g_ptr[NN + 1];
__device__ int g_off[NN];
__device__ int g_csr_src[NE];
__device__ int g_mode_ei;
__device__ int g_mode_b;

__device__ __forceinline__ void red_add_v4(float* p, float4 v) {
    asm volatile("red.global.add.v4.f32 [%0], {%1, %2, %3, %4};"
                 :: "l"(p), "f"(v.x), "f"(v.y), "f"(v.z), "f"(v.w)
                 : "memory");
}
__device__ __forceinline__ uint32_t f2tf32(float f) {
    uint32_t u;
    asm("cvt.rna.tf32.f32 %0, %1;" : "=r"(u) : "f"(f));
    return u;
}
__device__ __forceinline__ void mma_tf32(float& c0, float& c1, float& c2, float& c3,
                                         uint32_t a0, uint32_t a1, uint32_t a2, uint32_t a3,
                                         uint32_t b0, uint32_t b1) {
    asm volatile(
        "mma.sync.aligned.m16n8k8.row.col.f32.tf32.tf32.f32 "
        "{%0,%1,%2,%3}, {%4,%5,%6,%7}, {%8,%9}, {%0,%1,%2,%3};"
        : "+f"(c0), "+f"(c1), "+f"(c2), "+f"(c3)
        : "r"(a0), "r"(a1), "r"(a2), "r"(a3), "r"(b0), "r"(b1));
}

// ---------------- preamble ----------------
__global__ void flags_init_kernel() { g_mode_ei = 1; g_mode_b = 1; }

__global__ void detect_kernel(const int* __restrict__ ei32,
                              const int* __restrict__ b32) {
    int i = blockIdx.x * blockDim.x + threadIdx.x;
    int idx = 2 * i + 1;
    if (idx < 2 * NE) { if (ei32[idx] != 0) atomicExch(&g_mode_ei, 0); }
    if (idx < NN)     { if (b32[idx]  != 0) atomicExch(&g_mode_b, 0); }
}

__global__ void convert_kernel(const int* __restrict__ ei32,
                               const int* __restrict__ b32) {
    int i = blockIdx.x * blockDim.x + threadIdx.x;
    int m_ei = g_mode_ei, m_b = g_mode_b;
    if (i < NE) {
        g_src[i] = m_ei ? ei32[2 * i]        : ei32[i];
        g_dst[i] = m_ei ? ei32[2 * (NE + i)] : ei32[NE + i];
    }
    if (i < NN) g_batch[i] = m_b ? b32[2 * i] : b32[i];
}

__global__ void zero_kernel() {
    int i = blockIdx.x * blockDim.x + threadIdx.x;
    if (i < NG * NL * DD) g_pool[i] = 0.f;
    if (i < NN) g_deg[i] = 0;
    if (i < NL * DD) { g_sum[i] = 0.f; g_sqs[i] = 0.f; }
}

__global__ void hist_kernel() {
    int i = blockIdx.x * blockDim.x + threadIdx.x;
    if (i < NE) atomicAdd(&g_deg[g_dst[i]], 1);
}

__global__ void scan_kernel() {
    __shared__ int sh[1024];
    int t = threadIdx.x;
    const int CH = (NN + 1023) / 1024;
    int b0 = t * CH, b1 = min(b0 + CH, NN);
    int s = 0;
    for (int i = b0; i < b1; i++) s += g_deg[i];
    sh[t] = s;
    __syncthreads();
    for (int off = 1; off < 1024; off <<= 1) {
        int v = (t >= off) ? sh[t - off] : 0;
        __syncthreads();
        sh[t] += v;
        __syncthreads();
    }
    int run = (t > 0) ? sh[t - 1] : 0;
    for (int i = b0; i < b1; i++) {
        g_ptr[i] = run; g_off[i] = run;
        run += g_deg[i];
    }
    if (t == 0) g_ptr[NN] = NE;
}

__global__ void scatter_kernel() {
    int i = blockIdx.x * blockDim.x + threadIdx.x;
    if (i >= NE) return;
    int d = g_dst[i];
    int pos = atomicAdd(&g_off[d], 1);
    g_csr_src[pos] = g_src[i];
}

__global__ void wprep_kernel(const float* __restrict__ W1,
                             const float* __restrict__ W2) {
    int i = blockIdx.x * blockDim.x + threadIdx.x;
    if (i >= 2 * NL * DD * DD) return;
    int which = i / (NL * DD * DD);
    int r = i % (NL * DD * DD);
    int l = r / (DD * DD);
    int e = r % (DD * DD);
    int k = e / DD, n = e % DD;
    const float* w = which ? W2 : W1;
    g_Wt[which][l][n * AST + k] = f2tf32(w[l * DD * DD + k * DD + n]);
}

// ---------------- fused (1+eps)*h + CSR neighbor-sum ----------------
__global__ void agg_kernel(const float* __restrict__ x,
                           const float* __restrict__ eps, int l) {
    int warp = (blockIdx.x * blockDim.x + threadIdx.x) >> 5;
    if (warp >= NN) return;
    int lane = threadIdx.x & 31;
    const float* h = l ? g_H : x;
    const float4* hv = (const float4*)h;
    float e = 1.0f + __ldg(&eps[l]);
    float4 a = hv[warp * 32 + lane];
    float4 acc = make_float4(a.x * e, a.y * e, a.z * e, a.w * e);
    int p = __ldg(&g_ptr[warp]);
    int p1 = __ldg(&g_ptr[warp + 1]);
    for (; p + 4 <= p1; p += 4) {
        int s0 = __ldg(&g_csr_src[p]);
        int s1 = __ldg(&g_csr_src[p + 1]);
        int s2 = __ldg(&g_csr_src[p + 2]);
        int s3 = __ldg(&g_csr_src[p + 3]);
        float4 v0 = __ldg(&hv[s0 * 32 + lane]);
        float4 v1 = __ldg(&hv[s1 * 32 + lane]);
        float4 v2 = __ldg(&hv[s2 * 32 + lane]);
        float4 v3 = __ldg(&hv[s3 * 32 + lane]);
        acc.x += v0.x + v1.x + v2.x + v3.x;
        acc.y += v0.y + v1.y + v2.y + v3.y;
        acc.z += v0.z + v1.z + v2.z + v3.z;
        acc.w += v0.w + v1.w + v2.w + v3.w;
    }
    for (; p < p1; p++) {
        int s = __ldg(&g_csr_src[p]);
        float4 v = __ldg(&hv[s * 32 + lane]);
        acc.x += v.x; acc.y += v.y; acc.z += v.z; acc.w += v.w;
    }
    ((float4*)g_Z)[warp * 32 + lane] = acc;
}

// ---------------- mma.sync tf32 GEMM (M tile = 64, 2 CTAs/SM) ----------------
// 256 threads = 8 warps, warp tile 32x32 (wm = (wid&1)*32, wn = (wid>>1)*32)
#define SMEM_GEMM ((MT * AST + DD * AST) * 4)

template<bool RELU, bool STATS>
__global__ __launch_bounds__(256)
void gemm_mma_kernel(const uint32_t* __restrict__ Wt,
                     const float* __restrict__ bias,
                     const float* __restrict__ Ain,
                     float* __restrict__ Cout,
                     int l) {
    extern __shared__ __align__(16) uint32_t smem[];
    uint32_t* As = smem;             // [64][AST]
    uint32_t* Bs = smem + MT * AST;  // [128][AST] n-major
    int tid = threadIdx.x;
    int row0 = blockIdx.x * MT;

    #pragma unroll 4
    for (int i = tid; i < DD * AST / 4; i += 256)
        ((uint4*)Bs)[i] = ((const uint4*)Wt)[i];
    #pragma unroll 2
    for (int i = tid; i < MT * 32; i += 256) {
        int m = i >> 5;
        int k4 = i & 31;
        int gm = row0 + m;
        float4 v = make_float4(0.f, 0.f, 0.f, 0.f);
        if (gm < NN) v = ((const float4*)(Ain + (size_t)gm * DD))[k4];
        uint32_t* p = &As[m * AST + k4 * 4];
        p[0] = f2tf32(v.x); p[1] = f2tf32(v.y);
        p[2] = f2tf32(v.z); p[3] = f2tf32(v.w);
    }
    __syncthreads();

    int wid = tid >> 5, lane = tid & 31;
    int wm = (wid & 1) * 32;
    int wn = (wid >> 1) * 32;
    int grp = lane >> 2, qid = lane & 3;

    float acc[2][4][4];
    #pragma unroll
    for (int i = 0; i < 2; i++)
        #pragma unroll
        for (int j = 0; j < 4; j++)
            #pragma unroll
            for (int q = 0; q < 4; q++) acc[i][j][q] = 0.f;

    #pragma unroll
    for (int ks = 0; ks < 16; ks++) {
        int k0 = ks * 8;
        uint32_t a[2][4];
        #pragma unroll
        for (int mt = 0; mt < 2; mt++) {
            int r = wm + mt * 16;
            a[mt][0] = As[(r + grp) * AST + k0 + qid];
            a[mt][1] = As[(r + grp + 8) * AST + k0 + qid];
            a[mt][2] = As[(r + grp) * AST + k0 + qid + 4];
            a[mt][3] = As[(r + grp + 8) * AST + k0 + qid + 4];
        }
        #pragma unroll
        for (int nt = 0; nt < 4; nt++) {
            uint32_t b0 = Bs[(wn + nt * 8 + grp) * AST + k0 + qid];
            uint32_t b1 = Bs[(wn + nt * 8 + grp) * AST + k0 + qid + 4];
            #pragma unroll
            for (int mt = 0; mt < 2; mt++)
                mma_tf32(acc[mt][nt][0], acc[mt][nt][1], acc[mt][nt][2], acc[mt][nt][3],
                         a[mt][0], a[mt][1], a[mt][2], a[mt][3], b0, b1);
        }
    }

    #pragma unroll
    for (int nt = 0; nt < 4; nt++) {
        int col = wn + nt * 8 + 2 * qid;
        float bv0 = __ldg(&bias[col]);
        float bv1 = __ldg(&bias[col + 1]);
        float s0 = 0.f, s1 = 0.f, q0 = 0.f, q1 = 0.f;
        #pragma unroll
        for (int mt = 0; mt < 2; mt++) {
            int r = row0 + wm + mt * 16 + grp;
            float v0 = acc[mt][nt][0] + bv0;
            float v1 = acc[mt][nt][1] + bv1;
            float v2 = acc[mt][nt][2] + bv0;
            float v3 = acc[mt][nt][3] + bv1;
            if (RELU) {
                v0 = fmaxf(v0, 0.f); v1 = fmaxf(v1, 0.f);
                v2 = fmaxf(v2, 0.f); v3 = fmaxf(v3, 0.f);
            }
            if (r < NN) {
                *(float2*)(Cout + (size_t)r * DD + col) = make_float2(v0, v1);
                if (STATS) { s0 += v0; s1 += v1; q0 += v0 * v0; q1 += v1 * v1; }
            }
            if (r + 8 < NN) {
                *(float2*)(Cout + (size_t)(r + 8) * DD + col) = make_float2(v2, v3);
                if (STATS) { s0 += v2; s1 += v3; q0 += v2 * v2; q1 += v3 * v3; }
            }
        }
        if (STATS) {
            // reduce over grp lanes (same qid): xor masks 4, 8, 16
            #pragma unroll
            for (int m = 4; m < 32; m <<= 1) {
                s0 += __shfl_xor_sync(0xFFFFFFFF, s0, m);
                s1 += __shfl_xor_sync(0xFFFFFFFF, s1, m);
                q0 += __shfl_xor_sync(0xFFFFFFFF, q0, m);
                q1 += __shfl_xor_sync(0xFFFFFFFF, q1, m);
            }
            if (grp == 0) {
                atomicAdd(&g_sum[l * DD + col], s0);
                atomicAdd(&g_sum[l * DD + col + 1], s1);
                atomicAdd(&g_sqs[l * DD + col], q0);
                atomicAdd(&g_sqs[l * DD + col + 1], q1);
            }
        }
    }
}

// ---------------- BN finalize + relu + pool (fused) ----------------
__global__ void bn_relu_pool_kernel(const float* __restrict__ gamma,
                                    const float* __restrict__ beta, int l) {
    __shared__ float s_sc[DD], s_sf[DD];
    int tid = threadIdx.x;
    if (tid < DD) {
        float mean = g_sum[l * DD + tid] * (1.0f / NN);
        float var = g_sqs[l * DD + tid] * (1.0f / NN) - mean * mean;
        float sc = __ldg(&gamma[l * DD + tid]) * rsqrtf(var + 1e-5f);
        s_sc[tid] = sc;
        s_sf[tid] = __ldg(&beta[l * DD + tid]) - mean * sc;
    }
    __syncthreads();
    int i = blockIdx.x * blockDim.x + tid;
    if (i >= NN * DD / 4) return;
    int r = i >> 5;
    int c4 = (i & 31) << 2;
    float4 z = ((const float4*)g_Z)[i];
    float4 hv;
    hv.x = fmaxf(z.x * s_sc[c4]     + s_sf[c4],     0.f);
    hv.y = fmaxf(z.y * s_sc[c4 + 1] + s_sf[c4 + 1], 0.f);
    hv.z = fmaxf(z.z * s_sc[c4 + 2] + s_sf[c4 + 2], 0.f);
    hv.w = fmaxf(z.w * s_sc[c4 + 3] + s_sf[c4 + 3], 0.f);
    ((float4*)g_H)[i] = hv;
    int b = __ldg(&g_batch[r]);
    red_add_v4(&g_pool[(size_t)b * (NL * DD) + l * DD + c4], hv);
}

// ---------------- final linear ----------------
__global__ void final_kernel(const float* __restrict__ Wlin,
                             const float* __restrict__ blin,
                             float* __restrict__ out) {
    int t = blockIdx.x * blockDim.x + threadIdx.x;
    if (t >= NG * NC) return;
    int gph = t / NC, c = t % NC;
    float acc = __ldg(&blin[c]);
    const float* prow = &g_pool[(size_t)gph * (NL * DD)];
    #pragma unroll 8
    for (int k = 0; k < NL * DD; k++)
        acc += __ldg(&prow[k]) * __ldg(&Wlin[k * NC + c]);
    out[gph * NC + c] = acc;
}

extern "C" void kernel_launch(void* const* d_in, const int* in_sizes, int n_in,
                              void* d_out, int out_size) {
    const float* x     = (const float*)d_in[0];
    const int*   ei32  = (const int*)d_in[1];
    const int*   b32   = (const int*)d_in[2];
    const float* W1    = (const float*)d_in[3];
    const float* b1    = (const float*)d_in[4];
    const float* W2    = (const float*)d_in[5];
    const float* b2    = (const float*)d_in[6];
    const float* eps   = (const float*)d_in[7];
    const float* gamma = (const float*)d_in[8];
    const float* beta  = (const float*)d_in[9];
    const float* Wlin  = (const float*)d_in[10];
    const float* blin  = (const float*)d_in[11];
    float* out = (float*)d_out;

    cudaFuncSetAttribute(gemm_mma_kernel<true, false>,
                         cudaFuncAttributeMaxDynamicSharedMemorySize, SMEM_GEMM);
    cudaFuncSetAttribute(gemm_mma_kernel<false, true>,
                         cudaFuncAttributeMaxDynamicSharedMemorySize, SMEM_GEMM);

    flags_init_kernel<<<1, 1>>>();
    detect_kernel<<<(NE + 255) / 256, 256>>>(ei32, b32);
    convert_kernel<<<(NE + 255) / 256, 256>>>(ei32, b32);
    zero_kernel<<<(NG * NL * DD + 255) / 256, 256>>>();
    hist_kernel<<<(NE + 255) / 256, 256>>>();
    scan_kernel<<<1, 1024>>>();
    scatter_kernel<<<(NE + 255) / 256, 256>>>();
    wprep_kernel<<<(2 * NL * DD * DD + 255) / 256, 256>>>(W1, W2);

    int zgrid = (NN * DD / 4 + 255) / 256;
    int agrid = (NN * 32 + 255) / 256;
    int ggrid = (NN + MT - 1) / MT;   // 782

    uint32_t* wt_base;
    cudaGetSymbolAddress((void**)&wt_base, g_Wt);
    float *zb, *tb;
    cudaGetSymbolAddress((void**)&zb, g_Z);
    cudaGetSymbolAddress((void**)&tb, g_T);

    for (int l = 0; l < NL; l++) {
        agg_kernel<<<agrid, 256>>>(x, eps, l);
        gemm_mma_kernel<true, false><<<ggrid, 256, SMEM_GEMM>>>(
            wt_base + (size_t)l * DD * AST, b1 + l * DD, zb, tb, l);        // T = relu(Z@W1+b1)
        gemm_mma_kernel<false, true><<<ggrid, 256, SMEM_GEMM>>>(
            wt_base + (size_t)(NL + l) * DD * AST, b2 + l * DD, tb, zb, l); // Z = T@W2+b2 (+stats)
        bn_relu_pool_kernel<<<zgrid, 256>>>(gamma, beta, l);
    }
    final_kernel<<<(NG * NC + 255) / 256, 256>>>(Wlin, blin, out);
}